// round 2
// baseline (speedup 1.0000x reference)
#include <cuda_runtime.h>
#include <cstdint>

typedef unsigned long long ull;

// ---------------- scratch (device globals; no allocation allowed) ----------
__device__ float g_W[64 * 1024];     // folded weights, layout [c][e] (e fastest)
__device__ float g_u[16 * 1024];     // [b][c]  = Wc[:,C:] @ cond_b
__device__ float g_bias[16 * 64];    // [b][e]
__device__ float g_imp[64];
__device__ unsigned int g_cnt[64];

// ---------------- packed fp32x2 helpers ------------------------------------
#define PACK2(dst, f) asm("mov.b64 %0, {%1, %1};" : "=l"(dst) : "f"(f))
#define UNPACK2(lo, hi, src) asm("mov.b64 {%0, %1}, %2;" : "=f"(lo), "=f"(hi) : "l"(src))
#define FMA2(d, a, b, c) asm("fma.rn.f32x2 %0, %1, %2, %3;" : "=l"(d) : "l"(a), "l"(b), "l"(c))

__device__ __forceinline__ float warpReduceSum(float v) {
    #pragma unroll
    for (int o = 16; o; o >>= 1) v += __shfl_xor_sync(0xffffffffu, v, o);
    return v;
}

// ---------------- kernel 0: zero scratch -----------------------------------
__global__ void k_init(int nW) {
    int i = blockIdx.x * blockDim.x + threadIdx.x;
    if (i < nW) g_W[i] = 0.0f;
    if (i < 64) { g_imp[i] = 0.0f; g_cnt[i] = 0u; }
}

// ---------------- kernel 1: Wx[e][c] = sum_c' Wg[e][c'] * Wc[c'][c] --------
// grid: (C/16 c-tiles, 4 k-splits), block 256. Stored as g_W[c*64 + e].
__global__ void k_wx(const float* __restrict__ Wg, const float* __restrict__ Wc,
                     int C) {
    const int c0 = blockIdx.x * 16;
    const int kbase = blockIdx.y * (C / 4);
    const int t = threadIdx.x;
    __shared__ float wg_s[64 * 65];
    __shared__ float wc_s[64 * 17];
    float acc[4] = {0.f, 0.f, 0.f, 0.f};
    const int e = t & 63;
    const int cq = t >> 6;  // 0..3
    for (int kc = 0; kc < C / 4; kc += 64) {
        #pragma unroll
        for (int r = 0; r < 16; ++r) {
            int flat = r * 256 + t;
            int ee = flat >> 6, j = flat & 63;
            wg_s[ee * 65 + j] = Wg[(size_t)ee * C + kbase + kc + j];
        }
        #pragma unroll
        for (int r = 0; r < 4; ++r) {
            int flat = r * 256 + t;
            int j = flat >> 4, i = flat & 15;
            wc_s[j * 17 + i] = Wc[(size_t)(kbase + kc + j) * (2 * C) + c0 + i];
        }
        __syncthreads();
        #pragma unroll 8
        for (int j = 0; j < 64; ++j) {
            float w = wg_s[e * 65 + j];
            #pragma unroll
            for (int q = 0; q < 4; ++q)
                acc[q] += w * wc_s[j * 17 + cq * 4 + q];
        }
        __syncthreads();
    }
    #pragma unroll
    for (int q = 0; q < 4; ++q)
        atomicAdd(&g_W[(c0 + cq * 4 + q) * 64 + e], acc[q]);
}

// ---------------- kernel 2a: u[b][c'] = sum_d Wc[c'][C+d] * cond[b][d] -----
__global__ void k_u(const float* __restrict__ Wc, const float* __restrict__ cond,
                    int C) {
    int b = blockIdx.y;
    int w = threadIdx.x >> 5, lane = threadIdx.x & 31;
    int cp = blockIdx.x * 8 + w;
    const float* row = Wc + (size_t)cp * (2 * C) + C;
    const float* cb = cond + (size_t)b * C;
    float s = 0.f;
    for (int c = lane; c < C; c += 32) s += row[c] * cb[c];
    s = warpReduceSum(s);
    if (lane == 0) g_u[b * C + cp] = s;
}

// ---------------- kernel 2b: bias[b][e] = sum_c Wg[e][c] * u[b][c] ---------
__global__ void k_bias(const float* __restrict__ Wg, int C, int E) {
    int b = blockIdx.y;
    int w = threadIdx.x >> 5, lane = threadIdx.x & 31;
    int e = blockIdx.x * 8 + w;
    const float* wr = Wg + (size_t)e * C;
    const float* ub = g_u + (size_t)b * C;
    float s = 0.f;
    for (int c = lane; c < C; c += 32) s += wr[c] * ub[c];
    s = warpReduceSum(s);
    if (lane == 0) g_bias[b * E + e] = s;
}

// ---------------- kernel 3: main GEMM + fused router epilogue --------------
// logits[t][e] = sum_c x[t][c]*g_W[c][e] + bias[b][e]; then softmax, top-2,
// probs, importance/count partials. BM=256 tokens/block, 256 thr,
// thread tile = 8 tokens x 8 experts via fma.rn.f32x2.
#define BM 256
#define KC 16
#define XSS 17

__global__ __launch_bounds__(256)
void k_main(const float* __restrict__ x, float* __restrict__ out,
            int BT, int T, int C, int nkt) {
    __shared__ float xs[BM * XSS];
    __shared__ __align__(16) float ws[KC * 64];
    __shared__ float s_imp[64];
    __shared__ unsigned s_cnt[64];

    const int t = threadIdx.x;
    if (t < 64) { s_imp[t] = 0.f; s_cnt[t] = 0u; }

    const int tok0 = blockIdx.x * BM;
    const int c4 = t & 3, trow = t >> 2;
    const int eg = t & 7, tg = t >> 3;

    float4 xf[4];
    float4 wf;

    // prefetch tile 0
    {
        #pragma unroll
        for (int r = 0; r < 4; ++r) {
            int tok = tok0 + trow + r * 64;
            if (tok >= BT) tok = BT - 1;
            xf[r] = *(const float4*)(x + (size_t)tok * C + c4 * 4);
        }
        wf = ((const float4*)g_W)[t];
    }

    ull acc[8][4];
    #pragma unroll
    for (int i = 0; i < 8; ++i)
        #pragma unroll
        for (int p = 0; p < 4; ++p) acc[i][p] = 0ull;

    for (int kt = 0; kt < nkt; ++kt) {
        __syncthreads();
        #pragma unroll
        for (int r = 0; r < 4; ++r) {
            float* d = xs + (trow + r * 64) * XSS + c4 * 4;
            d[0] = xf[r].x; d[1] = xf[r].y; d[2] = xf[r].z; d[3] = xf[r].w;
        }
        ((float4*)ws)[t] = wf;
        __syncthreads();
        if (kt + 1 < nkt) {
            int kc = (kt + 1) * KC;
            #pragma unroll
            for (int r = 0; r < 4; ++r) {
                int tok = tok0 + trow + r * 64;
                if (tok >= BT) tok = BT - 1;
                xf[r] = *(const float4*)(x + (size_t)tok * C + kc + c4 * 4);
            }
            wf = ((const float4*)g_W)[(kt + 1) * 256 + t];
        }
        const float* xsp = xs + tg * 8 * XSS;
        #pragma unroll
        for (int k = 0; k < KC; ++k) {
            const ull* wrow = (const ull*)(ws + k * 64 + eg * 8);
            ull w0 = wrow[0], w1 = wrow[1], w2 = wrow[2], w3 = wrow[3];
            #pragma unroll
            for (int tt = 0; tt < 8; ++tt) {
                ull xp;
                PACK2(xp, xsp[tt * XSS + k]);
                FMA2(acc[tt][0], w0, xp, acc[tt][0]);
                FMA2(acc[tt][1], w1, xp, acc[tt][1]);
                FMA2(acc[tt][2], w2, xp, acc[tt][2]);
                FMA2(acc[tt][3], w3, xp, acc[tt][3]);
            }
        }
    }

    // -------------------- epilogue --------------------
    const int e0 = eg * 8;
    float* out_idx = out;
    float* out_sc  = out + (size_t)BT * 2;
    float* out_pr  = out + (size_t)BT * 4;
    float imp[8] = {0.f, 0.f, 0.f, 0.f, 0.f, 0.f, 0.f, 0.f};

    #pragma unroll
    for (int tt = 0; tt < 8; ++tt) {
        int tok = tok0 + tg * 8 + tt;
        bool valid = tok < BT;
        int tokc = valid ? tok : (BT - 1);
        int b = tokc / T;

        float lv[8];
        #pragma unroll
        for (int p = 0; p < 4; ++p) UNPACK2(lv[2 * p], lv[2 * p + 1], acc[tt][p]);
        #pragma unroll
        for (int j = 0; j < 8; ++j) lv[j] += g_bias[b * 64 + e0 + j];

        // local top-2 (ascending scan; ties keep lower index)
        float v1 = -1e30f, v2 = -1e30f;
        int i1 = 0, i2 = 0;
        #pragma unroll
        for (int j = 0; j < 8; ++j) {
            float v = lv[j];
            int e = e0 + j;
            if (v > v1) { v2 = v1; i2 = i1; v1 = v; i1 = e; }
            else if (v > v2) { v2 = v; i2 = e; }
        }
        // merge across the 8 lanes holding this token's 64 experts
        #pragma unroll
        for (int off = 1; off < 8; off <<= 1) {
            float ov1 = __shfl_xor_sync(0xffffffffu, v1, off);
            int   oi1 = __shfl_xor_sync(0xffffffffu, i1, off);
            float ov2 = __shfl_xor_sync(0xffffffffu, v2, off);
            int   oi2 = __shfl_xor_sync(0xffffffffu, i2, off);
            bool ob1 = (ov1 > v1) || (ov1 == v1 && oi1 < i1);
            if (ob1) {
                bool mb = (v1 > ov2) || (v1 == ov2 && i1 < oi2);
                if (mb) { v2 = v1; i2 = i1; } else { v2 = ov2; i2 = oi2; }
                v1 = ov1; i1 = oi1;
            } else {
                bool ob2 = (ov1 > v2) || (ov1 == v2 && oi1 < i2);
                if (ob2) { v2 = ov1; i2 = oi1; }
            }
        }

        // softmax over 64 (max == v1)
        float p[8], s = 0.f;
        #pragma unroll
        for (int j = 0; j < 8; ++j) { p[j] = __expf(lv[j] - v1); s += p[j]; }
        #pragma unroll
        for (int off = 1; off < 8; off <<= 1) s += __shfl_xor_sync(0xffffffffu, s, off);
        float inv = 1.0f / s;
        #pragma unroll
        for (int j = 0; j < 8; ++j) { p[j] *= inv; }

        if (valid) {
            #pragma unroll
            for (int j = 0; j < 8; ++j) imp[j] += p[j];
            float4* pp = (float4*)(out_pr + (size_t)tok * 64 + e0);
            pp[0] = make_float4(p[0], p[1], p[2], p[3]);
            pp[1] = make_float4(p[4], p[5], p[6], p[7]);
            if (eg == 0) {
                out_idx[tok * 2]     = (float)i1;
                out_idx[tok * 2 + 1] = (float)i2;
                float s1 = 1.0f / (1.0f + __expf(v2 - v1));
                out_sc[tok * 2]     = s1;
                out_sc[tok * 2 + 1] = 1.0f - s1;
                atomicAdd(&s_cnt[i1], 1u);
                atomicAdd(&s_cnt[i2], 1u);
            }
        }
    }

    #pragma unroll
    for (int j = 0; j < 8; ++j) atomicAdd(&s_imp[e0 + j], imp[j]);
    __syncthreads();
    if (t < 64) {
        atomicAdd(&g_imp[t], s_imp[t]);
        atomicAdd(&g_cnt[t], s_cnt[t]);
    }
}

// ---------------- kernel 4: finalize importance / load ---------------------
__global__ void k_final(float* __restrict__ out, int BT) {
    __shared__ float ssum;
    int e = threadIdx.x;
    if (e == 0) {
        float s = 0.f;
        for (int i = 0; i < 64; ++i) s += (float)g_cnt[i];
        ssum = s > 1.0f ? s : 1.0f;
    }
    __syncthreads();
    float* out_imp  = out + (size_t)BT * 4 + (size_t)BT * 64;
    float* out_load = out_imp + 64;
    if (e < 64) {
        out_imp[e]  = g_imp[e] / (float)BT;
        out_load[e] = (float)g_cnt[e] / ssum;
    }
}

// ---------------- launch ----------------------------------------------------
extern "C" void kernel_launch(void* const* d_in, const int* in_sizes, int n_in,
                              void* d_out, int out_size) {
    const float* x    = (const float*)d_in[0];
    const float* cond = (const float*)d_in[1];
    const float* Wg   = (const float*)d_in[2];
    const float* Wc   = (const float*)d_in[3];

    // derive shapes: Wc has C*2C elems, cond has B*C, x has B*T*C, Wg has E*C
    long long wcN = in_sizes[3];
    int C = 1;
    while ((long long)2 * C * C < wcN) C <<= 1;   // C is a power of two here (1024)
    int E = in_sizes[2] / C;                       // 64
    int B = in_sizes[1] / C;
    int T = in_sizes[0] / in_sizes[1];
    int BT = B * T;

    k_init<<<(E * C + 255) / 256, 256>>>(E * C);
    k_wx<<<dim3(C / 16, 4), 256>>>(Wg, Wc, C);
    k_u<<<dim3(C / 8, B), 256>>>(Wc, cond, C);
    k_bias<<<dim3(E / 8, B), 256>>>(Wg, C, E);
    k_main<<<(BT + BM - 1) / BM, 256>>>(x, (float*)d_out, BT, T, C, C / KC);
    k_final<<<1, 64>>>((float*)d_out, BT);
}

// round 3
// speedup vs baseline: 1.0084x; 1.0084x over previous
#include <cuda_runtime.h>
#include <cstdint>

typedef unsigned long long ull;

// ---------------- scratch (device globals; no allocation allowed) ----------
__device__ float g_W[64 * 1024];     // folded weights, layout [c][e] (e fastest)
__device__ float g_u[16 * 1024];     // [b][c]  = Wc[:,C:] @ cond_b
__device__ float g_bias[16 * 64];    // [b][e]
__device__ float g_imp[64];
__device__ unsigned int g_cnt[64];

// ---------------- packed fp32x2 helpers ------------------------------------
#define PACK2(dst, f) asm("mov.b64 %0, {%1, %1};" : "=l"(dst) : "f"(f))
#define UNPACK2(lo, hi, src) asm("mov.b64 {%0, %1}, %2;" : "=f"(lo), "=f"(hi) : "l"(src))
#define FMA2(d, a, b, c) asm("fma.rn.f32x2 %0, %1, %2, %3;" : "=l"(d) : "l"(a), "l"(b), "l"(c))

__device__ __forceinline__ float warpReduceSum(float v) {
    #pragma unroll
    for (int o = 16; o; o >>= 1) v += __shfl_xor_sync(0xffffffffu, v, o);
    return v;
}

// ---------------- kernel 0: zero scratch -----------------------------------
__global__ void k_init(int nW) {
    int i = blockIdx.x * blockDim.x + threadIdx.x;
    if (i < nW) g_W[i] = 0.0f;
    if (i < 64) { g_imp[i] = 0.0f; g_cnt[i] = 0u; }
}

// ---------------- kernel 1: Wx[e][c] = sum_c' Wg[e][c'] * Wc[c'][c] --------
// grid: (C/16 c-tiles, 4 k-splits), block 256. Stored as g_W[c*64 + e].
__global__ void k_wx(const float* __restrict__ Wg, const float* __restrict__ Wc,
                     int C) {
    const int c0 = blockIdx.x * 16;
    const int kbase = blockIdx.y * (C / 4);
    const int t = threadIdx.x;
    __shared__ float wg_s[64 * 65];
    __shared__ float wc_s[64 * 17];
    float acc[4] = {0.f, 0.f, 0.f, 0.f};
    const int e = t & 63;
    const int cq = t >> 6;  // 0..3
    for (int kc = 0; kc < C / 4; kc += 64) {
        #pragma unroll
        for (int r = 0; r < 16; ++r) {
            int flat = r * 256 + t;
            int ee = flat >> 6, j = flat & 63;
            wg_s[ee * 65 + j] = Wg[(size_t)ee * C + kbase + kc + j];
        }
        #pragma unroll
        for (int r = 0; r < 4; ++r) {
            int flat = r * 256 + t;
            int j = flat >> 4, i = flat & 15;
            wc_s[j * 17 + i] = Wc[(size_t)(kbase + kc + j) * (2 * C) + c0 + i];
        }
        __syncthreads();
        #pragma unroll 8
        for (int j = 0; j < 64; ++j) {
            float w = wg_s[e * 65 + j];
            #pragma unroll
            for (int q = 0; q < 4; ++q)
                acc[q] += w * wc_s[j * 17 + cq * 4 + q];
        }
        __syncthreads();
    }
    #pragma unroll
    for (int q = 0; q < 4; ++q)
        atomicAdd(&g_W[(c0 + cq * 4 + q) * 64 + e], acc[q]);
}

// ---------------- kernel 2a: u[b][c'] = sum_d Wc[c'][C+d] * cond[b][d] -----
__global__ void k_u(const float* __restrict__ Wc, const float* __restrict__ cond,
                    int C) {
    int b = blockIdx.y;
    int w = threadIdx.x >> 5, lane = threadIdx.x & 31;
    int cp = blockIdx.x * 8 + w;
    const float* row = Wc + (size_t)cp * (2 * C) + C;
    const float* cb = cond + (size_t)b * C;
    float s = 0.f;
    for (int c = lane; c < C; c += 32) s += row[c] * cb[c];
    s = warpReduceSum(s);
    if (lane == 0) g_u[b * C + cp] = s;
}

// ---------------- kernel 2b: bias[b][e] = sum_c Wg[e][c] * u[b][c] ---------
__global__ void k_bias(const float* __restrict__ Wg, int C, int E) {
    int b = blockIdx.y;
    int w = threadIdx.x >> 5, lane = threadIdx.x & 31;
    int e = blockIdx.x * 8 + w;
    const float* wr = Wg + (size_t)e * C;
    const float* ub = g_u + (size_t)b * C;
    float s = 0.f;
    for (int c = lane; c < C; c += 32) s += wr[c] * ub[c];
    s = warpReduceSum(s);
    if (lane == 0) g_bias[b * E + e] = s;
}

// ---------------- kernel 3: main GEMM + fused router epilogue --------------
// logits[t][e] = sum_c x[t][c]*g_W[c][e] + bias[b][e]; then softmax, top-2,
// probs, importance/count partials. BM=256 tokens/block, 256 thr,
// thread tile = 8 tokens x 8 experts via fma.rn.f32x2.
#define BM 256
#define KC 16
#define XSS 17

__global__ __launch_bounds__(256)
void k_main(const float* __restrict__ x, float* __restrict__ out,
            int BT, int T, int C, int nkt) {
    __shared__ float xs[BM * XSS];
    __shared__ __align__(16) float ws[KC * 64];
    __shared__ float s_imp[64];
    __shared__ unsigned s_cnt[64];

    const int t = threadIdx.x;
    if (t < 64) { s_imp[t] = 0.f; s_cnt[t] = 0u; }

    const int tok0 = blockIdx.x * BM;
    const int c4 = t & 3, trow = t >> 2;
    const int eg = t & 7, tg = t >> 3;

    float4 xf[4];
    float4 wf;

    // prefetch tile 0
    {
        #pragma unroll
        for (int r = 0; r < 4; ++r) {
            int tok = tok0 + trow + r * 64;
            if (tok >= BT) tok = BT - 1;
            xf[r] = *(const float4*)(x + (size_t)tok * C + c4 * 4);
        }
        wf = ((const float4*)g_W)[t];
    }

    ull acc[8][4];
    #pragma unroll
    for (int i = 0; i < 8; ++i)
        #pragma unroll
        for (int p = 0; p < 4; ++p) acc[i][p] = 0ull;

    for (int kt = 0; kt < nkt; ++kt) {
        __syncthreads();
        #pragma unroll
        for (int r = 0; r < 4; ++r) {
            float* d = xs + (trow + r * 64) * XSS + c4 * 4;
            d[0] = xf[r].x; d[1] = xf[r].y; d[2] = xf[r].z; d[3] = xf[r].w;
        }
        ((float4*)ws)[t] = wf;
        __syncthreads();
        if (kt + 1 < nkt) {
            int kc = (kt + 1) * KC;
            #pragma unroll
            for (int r = 0; r < 4; ++r) {
                int tok = tok0 + trow + r * 64;
                if (tok >= BT) tok = BT - 1;
                xf[r] = *(const float4*)(x + (size_t)tok * C + kc + c4 * 4);
            }
            wf = ((const float4*)g_W)[(kt + 1) * 256 + t];
        }
        const float* xsp = xs + tg * 8 * XSS;
        #pragma unroll
        for (int k = 0; k < KC; ++k) {
            const ull* wrow = (const ull*)(ws + k * 64 + eg * 8);
            ull w0 = wrow[0], w1 = wrow[1], w2 = wrow[2], w3 = wrow[3];
            #pragma unroll
            for (int tt = 0; tt < 8; ++tt) {
                ull xp;
                PACK2(xp, xsp[tt * XSS + k]);
                FMA2(acc[tt][0], w0, xp, acc[tt][0]);
                FMA2(acc[tt][1], w1, xp, acc[tt][1]);
                FMA2(acc[tt][2], w2, xp, acc[tt][2]);
                FMA2(acc[tt][3], w3, xp, acc[tt][3]);
            }
        }
    }

    // -------------------- epilogue --------------------
    const int e0 = eg * 8;
    float* out_idx = out;
    float* out_sc  = out + (size_t)BT * 2;
    float* out_pr  = out + (size_t)BT * 4;
    float imp[8] = {0.f, 0.f, 0.f, 0.f, 0.f, 0.f, 0.f, 0.f};

    #pragma unroll
    for (int tt = 0; tt < 8; ++tt) {
        int tok = tok0 + tg * 8 + tt;
        bool valid = tok < BT;
        int tokc = valid ? tok : (BT - 1);
        int b = tokc / T;

        float lv[8];
        #pragma unroll
        for (int p = 0; p < 4; ++p) UNPACK2(lv[2 * p], lv[2 * p + 1], acc[tt][p]);
        #pragma unroll
        for (int j = 0; j < 8; ++j) lv[j] += g_bias[b * 64 + e0 + j];

        // local top-2 (ascending scan; ties keep lower index)
        float v1 = -1e30f, v2 = -1e30f;
        int i1 = 0, i2 = 0;
        #pragma unroll
        for (int j = 0; j < 8; ++j) {
            float v = lv[j];
            int e = e0 + j;
            if (v > v1) { v2 = v1; i2 = i1; v1 = v; i1 = e; }
            else if (v > v2) { v2 = v; i2 = e; }
        }
        // merge across the 8 lanes holding this token's 64 experts
        #pragma unroll
        for (int off = 1; off < 8; off <<= 1) {
            float ov1 = __shfl_xor_sync(0xffffffffu, v1, off);
            int   oi1 = __shfl_xor_sync(0xffffffffu, i1, off);
            float ov2 = __shfl_xor_sync(0xffffffffu, v2, off);
            int   oi2 = __shfl_xor_sync(0xffffffffu, i2, off);
            bool ob1 = (ov1 > v1) || (ov1 == v1 && oi1 < i1);
            if (ob1) {
                bool mb = (v1 > ov2) || (v1 == ov2 && i1 < oi2);
                if (mb) { v2 = v1; i2 = i1; } else { v2 = ov2; i2 = oi2; }
                v1 = ov1; i1 = oi1;
            } else {
                bool ob2 = (ov1 > v2) || (ov1 == v2 && oi1 < i2);
                if (ob2) { v2 = ov1; i2 = oi1; }
            }
        }

        // softmax over 64 (max == v1)
        float p[8], s = 0.f;
        #pragma unroll
        for (int j = 0; j < 8; ++j) { p[j] = __expf(lv[j] - v1); s += p[j]; }
        #pragma unroll
        for (int off = 1; off < 8; off <<= 1) s += __shfl_xor_sync(0xffffffffu, s, off);
        float inv = 1.0f / s;
        #pragma unroll
        for (int j = 0; j < 8; ++j) { p[j] *= inv; }

        if (valid) {
            #pragma unroll
            for (int j = 0; j < 8; ++j) imp[j] += p[j];
            float4* pp = (float4*)(out_pr + (size_t)tok * 64 + e0);
            pp[0] = make_float4(p[0], p[1], p[2], p[3]);
            pp[1] = make_float4(p[4], p[5], p[6], p[7]);
            if (eg == 0) {
                out_idx[tok * 2]     = (float)i1;
                out_idx[tok * 2 + 1] = (float)i2;
                float s1 = 1.0f / (1.0f + __expf(v2 - v1));
                out_sc[tok * 2]     = s1;
                out_sc[tok * 2 + 1] = 1.0f - s1;
                atomicAdd(&s_cnt[i1], 1u);
                atomicAdd(&s_cnt[i2], 1u);
            }
        }
    }

    #pragma unroll
    for (int j = 0; j < 8; ++j) atomicAdd(&s_imp[e0 + j], imp[j]);
    __syncthreads();
    if (t < 64) {
        atomicAdd(&g_imp[t], s_imp[t]);
        atomicAdd(&g_cnt[t], s_cnt[t]);
    }
}

// ---------------- kernel 4: finalize importance / load ---------------------
__global__ void k_final(float* __restrict__ out, int BT) {
    __shared__ float ssum;
    int e = threadIdx.x;
    if (e == 0) {
        float s = 0.f;
        for (int i = 0; i < 64; ++i) s += (float)g_cnt[i];
        ssum = s > 1.0f ? s : 1.0f;
    }
    __syncthreads();
    float* out_imp  = out + (size_t)BT * 4 + (size_t)BT * 64;
    float* out_load = out_imp + 64;
    if (e < 64) {
        out_imp[e]  = g_imp[e] / (float)BT;
        out_load[e] = (float)g_cnt[e] / ssum;
    }
}

// ---------------- launch ----------------------------------------------------
extern "C" void kernel_launch(void* const* d_in, const int* in_sizes, int n_in,
                              void* d_out, int out_size) {
    const float* x    = (const float*)d_in[0];
    const float* cond = (const float*)d_in[1];
    const float* Wg   = (const float*)d_in[2];
    const float* Wc   = (const float*)d_in[3];

    // derive shapes: Wc has C*2C elems, cond has B*C, x has B*T*C, Wg has E*C
    long long wcN = in_sizes[3];
    int C = 1;
    while ((long long)2 * C * C < wcN) C <<= 1;   // C is a power of two here (1024)
    int E = in_sizes[2] / C;                       // 64
    int B = in_sizes[1] / C;
    int T = in_sizes[0] / in_sizes[1];
    int BT = B * T;

    k_init<<<(E * C + 255) / 256, 256>>>(E * C);
    k_wx<<<dim3(C / 16, 4), 256>>>(Wg, Wc, C);
    k_u<<<dim3(C / 8, B), 256>>>(Wc, cond, C);
    k_bias<<<dim3(E / 8, B), 256>>>(Wg, C, E);
    k_main<<<(BT + BM - 1) / BM, 256>>>(x, (float*)d_out, BT, T, C, C / KC);
    k_final<<<1, 64>>>((float*)d_out, BT);
}

// round 4
// speedup vs baseline: 1.0102x; 1.0018x over previous
#include <cuda_runtime.h>
#include <cstdint>

typedef unsigned long long ull;

// ---------------- scratch (device globals; no allocation allowed) ----------
__device__ float g_W[64 * 1024];     // folded weights, layout [c][e] (e fastest)
__device__ float g_u[16 * 1024];     // [b][c]  = Wc[:,C:] @ cond_b
__device__ float g_bias[16 * 64];    // [b][e]
__device__ float g_imp[64];
__device__ unsigned int g_cnt[64];

// ---------------- packed fp32x2 helpers ------------------------------------
#define PACK2(dst, f) asm("mov.b64 %0, {%1, %1};" : "=l"(dst) : "f"(f))
#define UNPACK2(lo, hi, src) asm("mov.b64 {%0, %1}, %2;" : "=f"(lo), "=f"(hi) : "l"(src))
#define FMA2(d, a, b, c) asm("fma.rn.f32x2 %0, %1, %2, %3;" : "=l"(d) : "l"(a), "l"(b), "l"(c))

__device__ __forceinline__ float warpReduceSum(float v) {
    #pragma unroll
    for (int o = 16; o; o >>= 1) v += __shfl_xor_sync(0xffffffffu, v, o);
    return v;
}

// ---------------- kernel 0: zero scratch -----------------------------------
__global__ void k_init(int nW) {
    int i = blockIdx.x * blockDim.x + threadIdx.x;
    if (i < nW) g_W[i] = 0.0f;
    if (i < 64) { g_imp[i] = 0.0f; g_cnt[i] = 0u; }
}

// ---------------- kernel 1: Wx[e][c] = sum_c' Wg[e][c'] * Wc[c'][c] --------
// grid: (C/16 c-tiles, 4 k-splits), block 256. Stored as g_W[c*64 + e].
__global__ void k_wx(const float* __restrict__ Wg, const float* __restrict__ Wc,
                     int C) {
    const int c0 = blockIdx.x * 16;
    const int kbase = blockIdx.y * (C / 4);
    const int t = threadIdx.x;
    __shared__ float wg_s[64 * 65];
    __shared__ float wc_s[64 * 17];
    float acc[4] = {0.f, 0.f, 0.f, 0.f};
    const int e = t & 63;
    const int cq = t >> 6;  // 0..3
    for (int kc = 0; kc < C / 4; kc += 64) {
        #pragma unroll
        for (int r = 0; r < 16; ++r) {
            int flat = r * 256 + t;
            int ee = flat >> 6, j = flat & 63;
            wg_s[ee * 65 + j] = Wg[(size_t)ee * C + kbase + kc + j];
        }
        #pragma unroll
        for (int r = 0; r < 4; ++r) {
            int flat = r * 256 + t;
            int j = flat >> 4, i = flat & 15;
            wc_s[j * 17 + i] = Wc[(size_t)(kbase + kc + j) * (2 * C) + c0 + i];
        }
        __syncthreads();
        #pragma unroll 8
        for (int j = 0; j < 64; ++j) {
            float w = wg_s[e * 65 + j];
            #pragma unroll
            for (int q = 0; q < 4; ++q)
                acc[q] += w * wc_s[j * 17 + cq * 4 + q];
        }
        __syncthreads();
    }
    #pragma unroll
    for (int q = 0; q < 4; ++q)
        atomicAdd(&g_W[(c0 + cq * 4 + q) * 64 + e], acc[q]);
}

// ---------------- kernel 2a: u[b][c'] = sum_d Wc[c'][C+d] * cond[b][d] -----
__global__ void k_u(const float* __restrict__ Wc, const float* __restrict__ cond,
                    int C) {
    int b = blockIdx.y;
    int w = threadIdx.x >> 5, lane = threadIdx.x & 31;
    int cp = blockIdx.x * 8 + w;
    const float* row = Wc + (size_t)cp * (2 * C) + C;
    const float* cb = cond + (size_t)b * C;
    float s = 0.f;
    for (int c = lane; c < C; c += 32) s += row[c] * cb[c];
    s = warpReduceSum(s);
    if (lane == 0) g_u[b * C + cp] = s;
}

// ---------------- kernel 2b: bias[b][e] = sum_c Wg[e][c] * u[b][c] ---------
__global__ void k_bias(const float* __restrict__ Wg, int C, int E) {
    int b = blockIdx.y;
    int w = threadIdx.x >> 5, lane = threadIdx.x & 31;
    int e = blockIdx.x * 8 + w;
    const float* wr = Wg + (size_t)e * C;
    const float* ub = g_u + (size_t)b * C;
    float s = 0.f;
    for (int c = lane; c < C; c += 32) s += wr[c] * ub[c];
    s = warpReduceSum(s);
    if (lane == 0) g_bias[b * E + e] = s;
}

// ---------------- kernel 3: main GEMM + fused router epilogue --------------
// logits[t][e] = sum_c x[t][c]*g_W[c][e] + bias[b][e]; then softmax, top-2,
// probs, importance/count partials. BM=256 tokens/block, 256 thr,
// thread tile = 8 tokens x 8 experts via fma.rn.f32x2.
#define BM 256
#define KC 16
#define XSS 17

__global__ __launch_bounds__(256)
void k_main(const float* __restrict__ x, float* __restrict__ out,
            int BT, int T, int C, int nkt) {
    __shared__ float xs[BM * XSS];
    __shared__ __align__(16) float ws[KC * 64];
    __shared__ float s_imp[64];
    __shared__ unsigned s_cnt[64];

    const int t = threadIdx.x;
    if (t < 64) { s_imp[t] = 0.f; s_cnt[t] = 0u; }

    const int tok0 = blockIdx.x * BM;
    const int c4 = t & 3, trow = t >> 2;
    const int eg = t & 7, tg = t >> 3;

    float4 xf[4];
    float4 wf;

    // prefetch tile 0
    {
        #pragma unroll
        for (int r = 0; r < 4; ++r) {
            int tok = tok0 + trow + r * 64;
            if (tok >= BT) tok = BT - 1;
            xf[r] = *(const float4*)(x + (size_t)tok * C + c4 * 4);
        }
        wf = ((const float4*)g_W)[t];
    }

    ull acc[8][4];
    #pragma unroll
    for (int i = 0; i < 8; ++i)
        #pragma unroll
        for (int p = 0; p < 4; ++p) acc[i][p] = 0ull;

    for (int kt = 0; kt < nkt; ++kt) {
        __syncthreads();
        #pragma unroll
        for (int r = 0; r < 4; ++r) {
            float* d = xs + (trow + r * 64) * XSS + c4 * 4;
            d[0] = xf[r].x; d[1] = xf[r].y; d[2] = xf[r].z; d[3] = xf[r].w;
        }
        ((float4*)ws)[t] = wf;
        __syncthreads();
        if (kt + 1 < nkt) {
            int kc = (kt + 1) * KC;
            #pragma unroll
            for (int r = 0; r < 4; ++r) {
                int tok = tok0 + trow + r * 64;
                if (tok >= BT) tok = BT - 1;
                xf[r] = *(const float4*)(x + (size_t)tok * C + kc + c4 * 4);
            }
            wf = ((const float4*)g_W)[(kt + 1) * 256 + t];
        }
        const float* xsp = xs + tg * 8 * XSS;
        #pragma unroll
        for (int k = 0; k < KC; ++k) {
            const ull* wrow = (const ull*)(ws + k * 64 + eg * 8);
            ull w0 = wrow[0], w1 = wrow[1], w2 = wrow[2], w3 = wrow[3];
            #pragma unroll
            for (int tt = 0; tt < 8; ++tt) {
                ull xp;
                PACK2(xp, xsp[tt * XSS + k]);
                FMA2(acc[tt][0], w0, xp, acc[tt][0]);
                FMA2(acc[tt][1], w1, xp, acc[tt][1]);
                FMA2(acc[tt][2], w2, xp, acc[tt][2]);
                FMA2(acc[tt][3], w3, xp, acc[tt][3]);
            }
        }
    }

    // -------------------- epilogue --------------------
    const int e0 = eg * 8;
    float* out_idx = out;
    float* out_sc  = out + (size_t)BT * 2;
    float* out_pr  = out + (size_t)BT * 4;
    float imp[8] = {0.f, 0.f, 0.f, 0.f, 0.f, 0.f, 0.f, 0.f};

    #pragma unroll
    for (int tt = 0; tt < 8; ++tt) {
        int tok = tok0 + tg * 8 + tt;
        bool valid = tok < BT;
        int tokc = valid ? tok : (BT - 1);
        int b = tokc / T;

        float lv[8];
        #pragma unroll
        for (int p = 0; p < 4; ++p) UNPACK2(lv[2 * p], lv[2 * p + 1], acc[tt][p]);
        #pragma unroll
        for (int j = 0; j < 8; ++j) lv[j] += g_bias[b * 64 + e0 + j];

        // local top-2 (ascending scan; ties keep lower index)
        float v1 = -1e30f, v2 = -1e30f;
        int i1 = 0, i2 = 0;
        #pragma unroll
        for (int j = 0; j < 8; ++j) {
            float v = lv[j];
            int e = e0 + j;
            if (v > v1) { v2 = v1; i2 = i1; v1 = v; i1 = e; }
            else if (v > v2) { v2 = v; i2 = e; }
        }
        // merge across the 8 lanes holding this token's 64 experts
        #pragma unroll
        for (int off = 1; off < 8; off <<= 1) {
            float ov1 = __shfl_xor_sync(0xffffffffu, v1, off);
            int   oi1 = __shfl_xor_sync(0xffffffffu, i1, off);
            float ov2 = __shfl_xor_sync(0xffffffffu, v2, off);
            int   oi2 = __shfl_xor_sync(0xffffffffu, i2, off);
            bool ob1 = (ov1 > v1) || (ov1 == v1 && oi1 < i1);
            if (ob1) {
                bool mb = (v1 > ov2) || (v1 == ov2 && i1 < oi2);
                if (mb) { v2 = v1; i2 = i1; } else { v2 = ov2; i2 = oi2; }
                v1 = ov1; i1 = oi1;
            } else {
                bool ob2 = (ov1 > v2) || (ov1 == v2 && oi1 < i2);
                if (ob2) { v2 = ov1; i2 = oi1; }
            }
        }

        // softmax over 64 (max == v1)
        float p[8], s = 0.f;
        #pragma unroll
        for (int j = 0; j < 8; ++j) { p[j] = __expf(lv[j] - v1); s += p[j]; }
        #pragma unroll
        for (int off = 1; off < 8; off <<= 1) s += __shfl_xor_sync(0xffffffffu, s, off);
        float inv = 1.0f / s;
        #pragma unroll
        for (int j = 0; j < 8; ++j) { p[j] *= inv; }

        if (valid) {
            #pragma unroll
            for (int j = 0; j < 8; ++j) imp[j] += p[j];
            float4* pp = (float4*)(out_pr + (size_t)tok * 64 + e0);
            pp[0] = make_float4(p[0], p[1], p[2], p[3]);
            pp[1] = make_float4(p[4], p[5], p[6], p[7]);
            if (eg == 0) {
                out_idx[tok * 2]     = (float)i1;
                out_idx[tok * 2 + 1] = (float)i2;
                float s1 = 1.0f / (1.0f + __expf(v2 - v1));
                out_sc[tok * 2]     = s1;
                out_sc[tok * 2 + 1] = 1.0f - s1;
                atomicAdd(&s_cnt[i1], 1u);
                atomicAdd(&s_cnt[i2], 1u);
            }
        }
    }

    #pragma unroll
    for (int j = 0; j < 8; ++j) atomicAdd(&s_imp[e0 + j], imp[j]);
    __syncthreads();
    if (t < 64) {
        atomicAdd(&g_imp[t], s_imp[t]);
        atomicAdd(&g_cnt[t], s_cnt[t]);
    }
}

// ---------------- kernel 4: finalize importance / load ---------------------
__global__ void k_final(float* __restrict__ out, int BT) {
    __shared__ float ssum;
    int e = threadIdx.x;
    if (e == 0) {
        float s = 0.f;
        for (int i = 0; i < 64; ++i) s += (float)g_cnt[i];
        ssum = s > 1.0f ? s : 1.0f;
    }
    __syncthreads();
    float* out_imp  = out + (size_t)BT * 4 + (size_t)BT * 64;
    float* out_load = out_imp + 64;
    if (e < 64) {
        out_imp[e]  = g_imp[e] / (float)BT;
        out_load[e] = (float)g_cnt[e] / ssum;
    }
}

// ---------------- launch ----------------------------------------------------
extern "C" void kernel_launch(void* const* d_in, const int* in_sizes, int n_in,
                              void* d_out, int out_size) {
    const float* x    = (const float*)d_in[0];
    const float* cond = (const float*)d_in[1];
    const float* Wg   = (const float*)d_in[2];
    const float* Wc   = (const float*)d_in[3];

    // derive shapes: Wc has C*2C elems, cond has B*C, x has B*T*C, Wg has E*C
    long long wcN = in_sizes[3];
    int C = 1;
    while ((long long)2 * C * C < wcN) C <<= 1;   // C is a power of two here (1024)
    int E = in_sizes[2] / C;                       // 64
    int B = in_sizes[1] / C;
    int T = in_sizes[0] / in_sizes[1];
    int BT = B * T;

    k_init<<<(E * C + 255) / 256, 256>>>(E * C);
    k_wx<<<dim3(C / 16, 4), 256>>>(Wg, Wc, C);
    k_u<<<dim3(C / 8, B), 256>>>(Wc, cond, C);
    k_bias<<<dim3(E / 8, B), 256>>>(Wg, C, E);
    k_main<<<(BT + BM - 1) / BM, 256>>>(x, (float*)d_out, BT, T, C, C / KC);
    k_final<<<1, 64>>>((float*)d_out, BT);
}